// round 13
// baseline (speedup 1.0000x reference)
#include <cuda_runtime.h>
#include <cuda_bf16.h>
#include <cstdint>

#define FULL 0xFFFFFFFFu
typedef unsigned long long u64;

static const int BB = 32;
static const int LL = 1024;
static const int DD = 1024;
static const int TT = 10;
static const int NROWS = BB * LL;           // 32768
static const int NSEG  = 16;                // segments per sequence
static const int SEGL  = 64;                // steps per segment
static const int KC    = 32;                // GEMM k-chunk
static const int KSPLIT = 4;
static const int KPB   = DD / KSPLIT;       // 256 k per block
static const int NCHUNK = KPB / KC;         // 8 chunks per block
static const int BM    = 64;                // block M tile

// Scratch (device globals; no runtime allocation)
__device__ float  g_W2T[32 * DD];           // repacked weights [o][k], tf32-rounded
__device__ float  g_Zp[KSPLIT][(size_t)NROWS * 32]; // K-split partial Z
__device__ float  g_em[(size_t)NROWS * 10]; // emissions (log domain, incl. bias)
__device__ float  g_F[(size_t)NROWS * 10];  // exp(em - c)
__device__ float  g_c[NROWS];               // per-row max emission
__device__ float  g_M[BB][NSEG][10][10];    // segment transfer: [b][s][col c][j]
__device__ float  g_sig[BB][NSEG][10];      // per-column log scale
__device__ float  g_cs[BB][NSEG];           // sum of c_l over masked steps in segment

__device__ __forceinline__ void cp_async16(uint32_t dst_smem, const void* src) {
    asm volatile("cp.async.cg.shared.global [%0], [%1], 16;" :: "r"(dst_smem), "l"(src));
}
__device__ __forceinline__ void cp_commit() { asm volatile("cp.async.commit_group;"); }
template <int N>
__device__ __forceinline__ void cp_wait() { asm volatile("cp.async.wait_group %0;" :: "n"(N)); }

__device__ __forceinline__ uint32_t to_tf32(float f) {
    uint32_t u;
    asm("cvt.rna.tf32.f32 %0, %1;" : "=r"(u) : "f"(f));
    return u;
}

// ---------------------------------------------------------------------------
// Repack conv_w (T, D, 3) -> W2T[o][k], o = t*3+tap, zero-pad o>=30, tf32-round
// Also zeroes the output accumulator (replaces a memset launch).
// ---------------------------------------------------------------------------
__global__ void repack_w2_kernel(const float* __restrict__ w, float* __restrict__ out) {
    int idx = blockIdx.x * blockDim.x + threadIdx.x;   // 32768 total
    if (idx == 0) out[0] = 0.f;
    int o = idx >> 10;
    int k = idx & 1023;
    float v = 0.f;
    if (o < 30) {
        int t = o / 3, tap = o % 3;
        v = w[((size_t)t * DD + k) * 3 + tap];
    }
    g_W2T[idx] = __uint_as_float(to_tf32(v));
}

// ---------------------------------------------------------------------------
// Conv as tf32 tensor-core GEMM, K-split: Zp[ks] = X[:, ks*256:+256] * W[...]
// Block: 128 thr = 4 warps; tile M=64 (warp m16), N=32, K=256 chunked by 32.
// 3-buffer cp.async pipeline, depth 2. A-frags fed raw (tf32 truncation).
// ---------------------------------------------------------------------------
__global__ void __launch_bounds__(128) conv_mma_kernel(const float* __restrict__ emb) {
    __shared__ float sX[3][BM][36];    // conflict-free: bank (4g+t+c)%32
    __shared__ float sWT[3][32][36];   // [o][k] layout, conflict-free B reads

    int tid  = threadIdx.x;
    int w    = tid >> 5;
    int lane = tid & 31;
    int g    = lane >> 2;     // groupID
    int t    = lane & 3;      // threadID in group
    int mtile = blockIdx.x >> 2;
    int ks    = blockIdx.x & 3;
    int k0    = ks * KPB;

    const float* Xg = emb + (size_t)mtile * BM * DD + k0;

    // A staging: 64 rows x 32 k = 512 float4 / 128 thr = 4 each
    int xr[4], xc[4];
    #pragma unroll
    for (int i = 0; i < 4; ++i) {
        int idx = tid + i * 128;
        xr[i] = idx >> 3;
        xc[i] = (idx & 7) * 4;
    }
    // W staging: 32 o-rows x 32 k = 256 float4 / 128 thr = 2 each
    int wo[2], wk[2];
    #pragma unroll
    for (int i = 0; i < 2; ++i) {
        int idx = tid + i * 128;
        wo[i] = idx >> 3;
        wk[i] = (idx & 7) * 4;
    }

    auto stage = [&](int c, int buf) {
        #pragma unroll
        for (int i = 0; i < 4; ++i)
            cp_async16((uint32_t)__cvta_generic_to_shared(&sX[buf][xr[i]][xc[i]]),
                       Xg + (size_t)xr[i] * DD + c * KC + xc[i]);
        #pragma unroll
        for (int i = 0; i < 2; ++i)
            cp_async16((uint32_t)__cvta_generic_to_shared(&sWT[buf][wo[i]][wk[i]]),
                       &g_W2T[wo[i] * DD + k0 + c * KC + wk[i]]);
        cp_commit();
    };

    float acc[4][4];
    #pragma unroll
    for (int n = 0; n < 4; ++n)
        #pragma unroll
        for (int i = 0; i < 4; ++i) acc[n][i] = 0.f;

    stage(0, 0);
    stage(1, 1);
    int buf = 0;
    for (int c = 0; c < NCHUNK; ++c) {
        if (c + 2 < NCHUNK) { stage(c + 2, (buf + 2) % 3); cp_wait<2>(); }
        else if (c + 1 < NCHUNK) cp_wait<1>();
        else cp_wait<0>();
        __syncthreads();

        #pragma unroll
        for (int s = 0; s < 4; ++s) {          // 4 k8-steps per chunk
            uint32_t a0 = __float_as_uint(sX[buf][w * 16 + g    ][s * 8 + t    ]);
            uint32_t a1 = __float_as_uint(sX[buf][w * 16 + g + 8][s * 8 + t    ]);
            uint32_t a2 = __float_as_uint(sX[buf][w * 16 + g    ][s * 8 + t + 4]);
            uint32_t a3 = __float_as_uint(sX[buf][w * 16 + g + 8][s * 8 + t + 4]);
            #pragma unroll
            for (int nt = 0; nt < 4; ++nt) {
                uint32_t b0 = __float_as_uint(sWT[buf][nt * 8 + g][s * 8 + t    ]);
                uint32_t b1 = __float_as_uint(sWT[buf][nt * 8 + g][s * 8 + t + 4]);
                asm("mma.sync.aligned.m16n8k8.row.col.f32.tf32.tf32.f32 "
                    "{%0,%1,%2,%3},{%4,%5,%6,%7},{%8,%9},{%0,%1,%2,%3};"
                    : "+f"(acc[nt][0]), "+f"(acc[nt][1]), "+f"(acc[nt][2]), "+f"(acc[nt][3])
                    : "r"(a0), "r"(a1), "r"(a2), "r"(a3), "r"(b0), "r"(b1));
            }
        }
        __syncthreads();
        buf = (buf + 1) % 3;
    }

    // epilogue: c0:(g,2t) c1:(g,2t+1) c2:(g+8,2t) c3:(g+8,2t+1)
    size_t row0 = (size_t)mtile * BM + w * 16;
    float* Zp = g_Zp[ks];
    #pragma unroll
    for (int nt = 0; nt < 4; ++nt) {
        float2* p0 = reinterpret_cast<float2*>(&Zp[(row0 + g    ) * 32 + nt * 8 + 2 * t]);
        float2* p1 = reinterpret_cast<float2*>(&Zp[(row0 + g + 8) * 32 + nt * 8 + 2 * t]);
        *p0 = make_float2(acc[nt][0], acc[nt][1]);
        *p1 = make_float2(acc[nt][2], acc[nt][3]);
    }
}

// ---------------------------------------------------------------------------
// Combine taps (sum K-split partials) + bias -> em; c = max_t em, F = exp(em-c)
// em[l][t] = Z[l-1][t*3+0] + Z[l][t*3+1] + Z[l+1][t*3+2] + b[t]
// ---------------------------------------------------------------------------
__global__ void combine_kernel(const float* __restrict__ conv_b) {
    int row = blockIdx.x * blockDim.x + threadIdx.x;   // < 32768
    int l = row & (LL - 1);
    float e[10];
    #pragma unroll
    for (int t = 0; t < 10; ++t) e[t] = conv_b[t];
    #pragma unroll
    for (int ks = 0; ks < KSPLIT; ++ks) {
        const float* Zc = &g_Zp[ks][(size_t)row * 32];
        #pragma unroll
        for (int t = 0; t < 10; ++t) {
            float v = Zc[t * 3 + 1];
            if (l > 0)      v += Zc[t * 3 - 32 + 0];
            if (l < LL - 1) v += Zc[t * 3 + 32 + 2];
            e[t] += v;
        }
    }
    float c = e[0];
    #pragma unroll
    for (int t = 1; t < 10; ++t) c = fmaxf(c, e[t]);
    g_c[row] = c;
    #pragma unroll
    for (int t = 0; t < 10; ++t) {
        g_em[(size_t)row * 10 + t] = e[t];
        g_F[(size_t)row * 10 + t]  = __expf(e[t] - c);
    }
}

// ---------------------------------------------------------------------------
// CRF segment scan, ILP=2: block = (batch, segment PAIR). 4 warps x 3 basis
// columns, each warp runs TWO independent chains (segments 2sp and 2sp+1)
// interleaved to hide the shfl->fma dependency latency.
// ---------------------------------------------------------------------------
__global__ void __launch_bounds__(128) crf_seg_kernel(
        const int* __restrict__ mask, const float* __restrict__ trans) {
    int sp   = blockIdx.x & (NSEG / 2 - 1);   // segment pair 0..7
    int b    = blockIdx.x / (NSEG / 2);
    int segA = sp * 2, segB = sp * 2 + 1;
    int w    = threadIdx.x >> 5;      // warp in block, 0..3
    int lane = threadIdx.x & 31;
    int grp  = lane / 10;             // 0..3 (3 => junk lanes)
    bool act = lane < 30;
    int j    = act ? (lane - grp * 10) : 0;
    int colv = w * 3 + (act ? grp : 0);
    bool store = act && colv < 10;
    int base_lane = act ? grp * 10 : 0;
    int base = b * LL;

    float E[10];
    #pragma unroll
    for (int i = 0; i < 10; ++i)
        E[i] = act ? __expf(__ldg(&trans[i * TT + j])) : 0.f;

    int tgt = store ? colv : 0;
    float qA = (act && j == tgt) ? 1.f : 0.f;
    float qB = qA;
    float sigA = 0.f, csA = 0.f, sigB = 0.f, csB = 0.f;

    int lA0 = segA * SEGL;
    int lB0 = segB * SEGL;

    for (int ch = 0; ch < 8; ++ch) {           // 8 chunks of 8 steps
        float fbA[8], cbA[8], fbB[8], cbB[8];
        int mbA[8], mbB[8];
        #pragma unroll
        for (int k = 0; k < 8; ++k) {
            int lA = lA0 + ch * 8 + k + 1;
            fbA[k] = act ? __ldg(&g_F[(size_t)(base + lA) * 10 + j]) : 1.f;
            cbA[k] = __ldg(&g_c[base + lA]);
            mbA[k] = __ldg(&mask[base + lA]);
            int lB = lB0 + ch * 8 + k + 1;
            bool vB = lB < LL;
            fbB[k] = (act && vB) ? __ldg(&g_F[(size_t)(base + lB) * 10 + j]) : 1.f;
            cbB[k] = vB ? __ldg(&g_c[base + lB]) : 0.f;
            mbB[k] = vB ? __ldg(&mask[base + lB]) : 0;
        }
        #pragma unroll
        for (int k = 0; k < 8; ++k) {
            float vA0 = 0.f, vA1 = 0.f, vB0 = 0.f, vB1 = 0.f;
            #pragma unroll
            for (int i = 0; i < 5; ++i) {
                vA0 = fmaf(__shfl_sync(FULL, qA, base_lane + i), E[i], vA0);
                vB0 = fmaf(__shfl_sync(FULL, qB, base_lane + i), E[i], vB0);
            }
            #pragma unroll
            for (int i = 5; i < 10; ++i) {
                vA1 = fmaf(__shfl_sync(FULL, qA, base_lane + i), E[i], vA1);
                vB1 = fmaf(__shfl_sync(FULL, qB, base_lane + i), E[i], vB1);
            }
            if (mbA[k]) { qA = (vA0 + vA1) * fbA[k]; csA += cbA[k]; }
            if (mbB[k]) { qB = (vB0 + vB1) * fbB[k]; csB += cbB[k]; }
        }
        if (ch & 1) {                           // renorm every 16 steps
            float sA = 0.f, sB = 0.f;
            #pragma unroll
            for (int i = 0; i < 10; ++i) {
                sA += __shfl_sync(FULL, qA, base_lane + i);
                sB += __shfl_sync(FULL, qB, base_lane + i);
            }
            sigA += __logf(sA); qA *= (1.0f / sA);
            sigB += __logf(sB); qB *= (1.0f / sB);
        }
    }

    if (store) {
        g_M[b][segA][colv][j] = qA;
        g_M[b][segB][colv][j] = qB;
        if (j == 0) {
            g_sig[b][segA][colv] = sigA;
            g_sig[b][segB][colv] = sigB;
        }
    }
    if (threadIdx.x == 0) {
        g_cs[b][segA] = csA;
        g_cs[b][segB] = csB;
    }
}

// ---------------------------------------------------------------------------
// CRF combine: block = one batch, 128 threads.
// 4 warps do the numerator cooperatively; M/sig/cs prefetched to smem; then
// warp 0 runs the 16 sequential matvec rounds from LDS.
// ---------------------------------------------------------------------------
__global__ void __launch_bounds__(128) crf_combine_kernel(
        const int* __restrict__ mask,
        const int* __restrict__ labels,
        const float* __restrict__ start_t,
        const float* __restrict__ end_t,
        const float* __restrict__ trans,
        float* __restrict__ out) {
    __shared__ float sM[NSEG][10][10];
    __shared__ float sSig[NSEG][10];
    __shared__ float sCs[NSEG];
    __shared__ float sNum[4];
    __shared__ int   sLen[4];

    int b = blockIdx.x;
    int tid = threadIdx.x;
    int w = tid >> 5;
    int lane = tid & 31;
    int base = b * LL;

    // prefetch segment data to smem (whole block)
    for (int i = tid; i < NSEG * 100; i += 128)
        ((float*)sM)[i] = __ldg(&(&g_M[b][0][0][0])[i]);
    for (int i = tid; i < NSEG * 10; i += 128)
        ((float*)sSig)[i] = __ldg(&(&g_sig[b][0][0])[i]);
    if (tid < NSEG) sCs[tid] = __ldg(&g_cs[b][tid]);

    // ---------------- numerator: 128 threads strided ----------------
    float numv = 0.f;
    int slen = 0;
    for (int l = tid; l < LL; l += 128) {
        int m = __ldg(&mask[base + l]);
        slen += (m != 0);
        if (l > 0 && m) {
            int lp = __ldg(&labels[base + l - 1]);
            int lc = __ldg(&labels[base + l]);
            numv += __ldg(&trans[lp * TT + lc]) + g_em[(size_t)(base + l) * 10 + lc];
        }
    }
    if (tid == 0) {
        int l0 = __ldg(&labels[base]);
        numv += __ldg(&start_t[l0]) + g_em[(size_t)base * 10 + l0];
    }
    #pragma unroll
    for (int off = 16; off; off >>= 1) {
        numv += __shfl_xor_sync(FULL, numv, off);
        slen += __shfl_xor_sync(FULL, slen, off);
    }
    if (lane == 0) { sNum[w] = numv; sLen[w] = slen; }
    __syncthreads();

    // ---------------- denominator: warp 0 only ----------------
    if (w == 0) {
        numv = sNum[0] + sNum[1] + sNum[2] + sNum[3];
        slen = sLen[0] + sLen[1] + sLen[2] + sLen[3];
        int last = __ldg(&labels[base + slen - 1]);
        numv += __ldg(&end_t[last]);

        bool act = (lane < TT);
        int j = act ? lane : 0;
        float q = act ? __expf(__ldg(&start_t[j])) * g_F[(size_t)base * 10 + j] : 0.f;
        float logA = g_c[base];

        for (int s = 0; s < NSEG; ++s) {
            float mrow[10];
            #pragma unroll
            for (int c = 0; c < 10; ++c)
                mrow[c] = act ? sM[s][c][j] : 0.f;
            float sg = (lane < 10) ? sSig[s][lane] : -1e30f;
            float sm = sg;
            #pragma unroll
            for (int off = 16; off; off >>= 1)
                sm = fmaxf(sm, __shfl_xor_sync(FULL, sm, off));
            float u = act ? q * __expf(sg - sm) : 0.f;
            float v = 0.f;
            #pragma unroll
            for (int c = 0; c < 10; ++c)
                v = fmaf(__shfl_sync(FULL, u, c), mrow[c], v);
            q = v;
            logA += sm + sCs[s];
            float ssum = q;
            #pragma unroll
            for (int off = 16; off; off >>= 1)
                ssum += __shfl_xor_sync(FULL, ssum, off);
            logA += __logf(ssum);
            q *= (1.0f / ssum);
        }

        float r = act ? q * __expf(__ldg(&end_t[j])) : 0.f;
        #pragma unroll
        for (int off = 16; off; off >>= 1) r += __shfl_xor_sync(FULL, r, off);
        float denom = logA + __logf(r);

        if (lane == 0) atomicAdd(out, -(numv - denom));
    }
}

// ---------------------------------------------------------------------------
extern "C" void kernel_launch(void* const* d_in, const int* in_sizes, int n_in,
                              void* d_out, int out_size) {
    const float* emb     = (const float*)d_in[0];  // (32,1024,1024) f32
    const int*   mask    = (const int*)  d_in[1];  // (32,1024) i32
    const int*   labels  = (const int*)  d_in[2];  // (32,1024) i32
    const float* conv_w  = (const float*)d_in[3];  // (10,1024,3)
    const float* conv_b  = (const float*)d_in[4];  // (10,)
    const float* start_t = (const float*)d_in[5];  // (10,)
    const float* end_t   = (const float*)d_in[6];  // (10,)
    const float* trans   = (const float*)d_in[7];  // (10,10)
    float* out = (float*)d_out;

    repack_w2_kernel<<<128, 256>>>(conv_w, out);      // also zeroes out[0]
    conv_mma_kernel<<<(NROWS / BM) * KSPLIT, 128>>>(emb);  // 2048 blocks
    combine_kernel<<<NROWS / 256, 256>>>(conv_b);
    crf_seg_kernel<<<BB * (NSEG / 2), 128>>>(mask, trans);  // 256 blocks, ILP=2
    crf_combine_kernel<<<BB, 128>>>(mask, labels, start_t, end_t, trans, out);
}

// round 14
// speedup vs baseline: 1.1051x; 1.1051x over previous
#include <cuda_runtime.h>
#include <cuda_bf16.h>
#include <cstdint>

#define FULL 0xFFFFFFFFu
typedef unsigned long long u64;

static const int BB = 32;
static const int LL = 1024;
static const int DD = 1024;
static const int TT = 10;
static const int NROWS = BB * LL;           // 32768
static const int NSEG  = 16;                // segments per sequence
static const int SEGL  = 64;                // steps per segment
static const int KC    = 32;                // GEMM k-chunk
static const int KSPLIT = 4;
static const int KPB   = DD / KSPLIT;       // 256 k per block
static const int NCHUNK = KPB / KC;         // 8 chunks per block
static const int BM    = 64;                // block M tile

// Scratch (device globals; no runtime allocation)
__device__ float  g_W2T[32 * DD];           // repacked weights [o][k], tf32-rounded
__device__ float  g_Zp[KSPLIT][(size_t)NROWS * 32]; // K-split partial Z
__device__ float  g_em[(size_t)NROWS * 10]; // emissions (log domain, incl. bias)
__device__ float  g_M[BB][NSEG][10][10];    // segment transfer: [b][s][col c][j]
__device__ float  g_sig[BB][NSEG][10];      // per-column log scale
__device__ float  g_cs[BB][NSEG];           // sum of c_l over masked steps in segment

__device__ __forceinline__ void cp_async16(uint32_t dst_smem, const void* src) {
    asm volatile("cp.async.cg.shared.global [%0], [%1], 16;" :: "r"(dst_smem), "l"(src));
}
__device__ __forceinline__ void cp_commit() { asm volatile("cp.async.commit_group;"); }
template <int N>
__device__ __forceinline__ void cp_wait() { asm volatile("cp.async.wait_group %0;" :: "n"(N)); }

__device__ __forceinline__ uint32_t to_tf32(float f) {
    uint32_t u;
    asm("cvt.rna.tf32.f32 %0, %1;" : "=r"(u) : "f"(f));
    return u;
}

// ---------------------------------------------------------------------------
// Repack conv_w (T, D, 3) -> W2T[o][k], o = t*3+tap, zero-pad o>=30, tf32-round
// Also zeroes the output accumulator (replaces a memset launch).
// ---------------------------------------------------------------------------
__global__ void repack_w2_kernel(const float* __restrict__ w, float* __restrict__ out) {
    int idx = blockIdx.x * blockDim.x + threadIdx.x;   // 32768 total
    if (idx == 0) out[0] = 0.f;
    int o = idx >> 10;
    int k = idx & 1023;
    float v = 0.f;
    if (o < 30) {
        int t = o / 3, tap = o % 3;
        v = w[((size_t)t * DD + k) * 3 + tap];
    }
    g_W2T[idx] = __uint_as_float(to_tf32(v));
}

// ---------------------------------------------------------------------------
// Conv as tf32 tensor-core GEMM, K-split: Zp[ks] = X[:, ks*256:+256] * W[...]
// Block: 128 thr = 4 warps; tile M=64 (warp m16), N=32, K=256 chunked by 32.
// 3-buffer cp.async pipeline, depth 2. A-frags fed raw (tf32 truncation).
// ---------------------------------------------------------------------------
__global__ void __launch_bounds__(128) conv_mma_kernel(const float* __restrict__ emb) {
    __shared__ float sX[3][BM][36];    // conflict-free: bank (4g+t+c)%32
    __shared__ float sWT[3][32][36];   // [o][k] layout, conflict-free B reads

    int tid  = threadIdx.x;
    int w    = tid >> 5;
    int lane = tid & 31;
    int g    = lane >> 2;     // groupID
    int t    = lane & 3;      // threadID in group
    int mtile = blockIdx.x >> 2;
    int ks    = blockIdx.x & 3;
    int k0    = ks * KPB;

    const float* Xg = emb + (size_t)mtile * BM * DD + k0;

    // A staging: 64 rows x 32 k = 512 float4 / 128 thr = 4 each
    int xr[4], xc[4];
    #pragma unroll
    for (int i = 0; i < 4; ++i) {
        int idx = tid + i * 128;
        xr[i] = idx >> 3;
        xc[i] = (idx & 7) * 4;
    }
    // W staging: 32 o-rows x 32 k = 256 float4 / 128 thr = 2 each
    int wo[2], wk[2];
    #pragma unroll
    for (int i = 0; i < 2; ++i) {
        int idx = tid + i * 128;
        wo[i] = idx >> 3;
        wk[i] = (idx & 7) * 4;
    }

    auto stage = [&](int c, int buf) {
        #pragma unroll
        for (int i = 0; i < 4; ++i)
            cp_async16((uint32_t)__cvta_generic_to_shared(&sX[buf][xr[i]][xc[i]]),
                       Xg + (size_t)xr[i] * DD + c * KC + xc[i]);
        #pragma unroll
        for (int i = 0; i < 2; ++i)
            cp_async16((uint32_t)__cvta_generic_to_shared(&sWT[buf][wo[i]][wk[i]]),
                       &g_W2T[wo[i] * DD + k0 + c * KC + wk[i]]);
        cp_commit();
    };

    float acc[4][4];
    #pragma unroll
    for (int n = 0; n < 4; ++n)
        #pragma unroll
        for (int i = 0; i < 4; ++i) acc[n][i] = 0.f;

    stage(0, 0);
    stage(1, 1);
    int buf = 0;
    for (int c = 0; c < NCHUNK; ++c) {
        if (c + 2 < NCHUNK) { stage(c + 2, (buf + 2) % 3); cp_wait<2>(); }
        else if (c + 1 < NCHUNK) cp_wait<1>();
        else cp_wait<0>();
        __syncthreads();

        #pragma unroll
        for (int s = 0; s < 4; ++s) {          // 4 k8-steps per chunk
            uint32_t a0 = __float_as_uint(sX[buf][w * 16 + g    ][s * 8 + t    ]);
            uint32_t a1 = __float_as_uint(sX[buf][w * 16 + g + 8][s * 8 + t    ]);
            uint32_t a2 = __float_as_uint(sX[buf][w * 16 + g    ][s * 8 + t + 4]);
            uint32_t a3 = __float_as_uint(sX[buf][w * 16 + g + 8][s * 8 + t + 4]);
            #pragma unroll
            for (int nt = 0; nt < 4; ++nt) {
                uint32_t b0 = __float_as_uint(sWT[buf][nt * 8 + g][s * 8 + t    ]);
                uint32_t b1 = __float_as_uint(sWT[buf][nt * 8 + g][s * 8 + t + 4]);
                asm("mma.sync.aligned.m16n8k8.row.col.f32.tf32.tf32.f32 "
                    "{%0,%1,%2,%3},{%4,%5,%6,%7},{%8,%9},{%0,%1,%2,%3};"
                    : "+f"(acc[nt][0]), "+f"(acc[nt][1]), "+f"(acc[nt][2]), "+f"(acc[nt][3])
                    : "r"(a0), "r"(a1), "r"(a2), "r"(a3), "r"(b0), "r"(b1));
            }
        }
        __syncthreads();
        buf = (buf + 1) % 3;
    }

    // epilogue: c0:(g,2t) c1:(g,2t+1) c2:(g+8,2t) c3:(g+8,2t+1)
    size_t row0 = (size_t)mtile * BM + w * 16;
    float* Zp = g_Zp[ks];
    #pragma unroll
    for (int nt = 0; nt < 4; ++nt) {
        float2* p0 = reinterpret_cast<float2*>(&Zp[(row0 + g    ) * 32 + nt * 8 + 2 * t]);
        float2* p1 = reinterpret_cast<float2*>(&Zp[(row0 + g + 8) * 32 + nt * 8 + 2 * t]);
        *p0 = make_float2(acc[nt][0], acc[nt][1]);
        *p1 = make_float2(acc[nt][2], acc[nt][3]);
    }
}

// ---------------------------------------------------------------------------
// Fused emissions + CRF segment scan. Block = one (batch, segment).
// Phase 1: threads 0..64 compute em rows l0..l0+64 from g_Zp into smem
//          (sF = exp(em - c), sC = c); write g_em for rows l0..l0+63.
// Phase 2: R12 scan (4 warps x 3 basis columns) reading F/c from smem.
// ---------------------------------------------------------------------------
__global__ void __launch_bounds__(128) crf_seg_kernel(
        const int* __restrict__ mask, const float* __restrict__ trans,
        const float* __restrict__ conv_b) {
    __shared__ float sF[SEGL + 1][10];
    __shared__ float sC[SEGL + 1];

    int seg  = blockIdx.x & (NSEG - 1);
    int b    = blockIdx.x / NSEG;
    int base = b * LL;
    int l0   = seg * SEGL;
    int tid  = threadIdx.x;

    // ---------------- phase 1: emissions into smem ----------------
    if (tid <= SEGL) {
        int l = l0 + tid;
        if (l < LL) {
            size_t row = base + l;
            float e[10];
            #pragma unroll
            for (int t = 0; t < 10; ++t) e[t] = __ldg(&conv_b[t]);
            #pragma unroll
            for (int ks = 0; ks < KSPLIT; ++ks) {
                const float* Zc = &g_Zp[ks][row * 32];
                #pragma unroll
                for (int t = 0; t < 10; ++t) {
                    float v = Zc[t * 3 + 1];
                    if (l > 0)      v += Zc[t * 3 - 32 + 0];
                    if (l < LL - 1) v += Zc[t * 3 + 32 + 2];
                    e[t] += v;
                }
            }
            float c = e[0];
            #pragma unroll
            for (int t = 1; t < 10; ++t) c = fmaxf(c, e[t]);
            sC[tid] = c;
            #pragma unroll
            for (int t = 0; t < 10; ++t) sF[tid][t] = __expf(e[t] - c);
            if (tid < SEGL) {       // each row written by exactly one block
                #pragma unroll
                for (int t = 0; t < 10; ++t) g_em[row * 10 + t] = e[t];
            }
        } else {
            sC[tid] = 0.f;
            #pragma unroll
            for (int t = 0; t < 10; ++t) sF[tid][t] = 1.f;
        }
    }
    __syncthreads();

    // ---------------- phase 2: basis-vector scan ----------------
    int w    = tid >> 5;              // warp 0..3
    int lane = tid & 31;
    int grp  = lane / 10;             // 0..3 (3 => junk lanes)
    bool act = lane < 30;
    int j    = act ? (lane - grp * 10) : 0;
    int colv = w * 3 + (act ? grp : 0);
    bool store = act && colv < 10;
    int base_lane = act ? grp * 10 : 0;

    float E[10];
    #pragma unroll
    for (int i = 0; i < 10; ++i)
        E[i] = act ? __expf(__ldg(&trans[i * TT + j])) : 0.f;

    int tgt = store ? colv : 0;
    float q = (act && j == tgt) ? 1.f : 0.f;
    float sig = 0.f, cs = 0.f;

    for (int ch = 0; ch < SEGL / 16; ++ch) {
        float fb[16], cb[16];
        int mb[16];
        #pragma unroll
        for (int k = 0; k < 16; ++k) {
            int r = ch * 16 + k + 1;          // row offset in segment, 1..64
            int l = l0 + r;
            fb[k] = sF[r][j];
            cb[k] = sC[r];
            mb[k] = (l < LL) ? __ldg(&mask[base + l]) : 0;
        }
        #pragma unroll
        for (int k = 0; k < 16; ++k) {
            float v0 = 0.f, v1 = 0.f;
            #pragma unroll
            for (int i = 0; i < 5; ++i)
                v0 = fmaf(__shfl_sync(FULL, q, base_lane + i), E[i], v0);
            #pragma unroll
            for (int i = 5; i < 10; ++i)
                v1 = fmaf(__shfl_sync(FULL, q, base_lane + i), E[i], v1);
            if (mb[k]) {                 // uniform across warp
                q = (v0 + v1) * fb[k];
                cs += cb[k];
            }
        }
        float s = 0.f;
        #pragma unroll
        for (int i = 0; i < 10; ++i)
            s += __shfl_sync(FULL, q, base_lane + i);
        sig += __logf(s);
        q *= (1.0f / s);
    }

    if (store) {
        g_M[b][seg][colv][j] = q;
        if (j == 0) g_sig[b][seg][colv] = sig;
    }
    if (tid == 0) g_cs[b][seg] = cs;
}

// ---------------------------------------------------------------------------
// CRF combine: block = one batch, 128 threads.
// 4 warps do the numerator cooperatively; M/sig/cs prefetched to smem; then
// warp 0 runs the 16 sequential matvec rounds from LDS.
// ---------------------------------------------------------------------------
__global__ void __launch_bounds__(128) crf_combine_kernel(
        const int* __restrict__ mask,
        const int* __restrict__ labels,
        const float* __restrict__ start_t,
        const float* __restrict__ end_t,
        const float* __restrict__ trans,
        float* __restrict__ out) {
    __shared__ float sM[NSEG][10][10];
    __shared__ float sSig[NSEG][10];
    __shared__ float sCs[NSEG];
    __shared__ float sNum[4];
    __shared__ int   sLen[4];

    int b = blockIdx.x;
    int tid = threadIdx.x;
    int w = tid >> 5;
    int lane = tid & 31;
    int base = b * LL;

    // prefetch segment data to smem (whole block)
    for (int i = tid; i < NSEG * 100; i += 128)
        ((float*)sM)[i] = __ldg(&(&g_M[b][0][0][0])[i]);
    for (int i = tid; i < NSEG * 10; i += 128)
        ((float*)sSig)[i] = __ldg(&(&g_sig[b][0][0])[i]);
    if (tid < NSEG) sCs[tid] = __ldg(&g_cs[b][tid]);

    // ---------------- numerator: 128 threads strided ----------------
    float numv = 0.f;
    int slen = 0;
    for (int l = tid; l < LL; l += 128) {
        int m = __ldg(&mask[base + l]);
        slen += (m != 0);
        if (l > 0 && m) {
            int lp = __ldg(&labels[base + l - 1]);
            int lc = __ldg(&labels[base + l]);
            numv += __ldg(&trans[lp * TT + lc]) + g_em[(size_t)(base + l) * 10 + lc];
        }
    }
    if (tid == 0) {
        int l0 = __ldg(&labels[base]);
        numv += __ldg(&start_t[l0]) + g_em[(size_t)base * 10 + l0];
    }
    #pragma unroll
    for (int off = 16; off; off >>= 1) {
        numv += __shfl_xor_sync(FULL, numv, off);
        slen += __shfl_xor_sync(FULL, slen, off);
    }
    if (lane == 0) { sNum[w] = numv; sLen[w] = slen; }
    __syncthreads();

    // ---------------- denominator: warp 0 only ----------------
    if (w == 0) {
        numv = sNum[0] + sNum[1] + sNum[2] + sNum[3];
        slen = sLen[0] + sLen[1] + sLen[2] + sLen[3];
        int last = __ldg(&labels[base + slen - 1]);
        numv += __ldg(&end_t[last]);

        bool act = (lane < TT);
        int j = act ? lane : 0;
        // init from em row 0 (compute scale inline)
        float e0 = (lane < TT) ? g_em[(size_t)base * 10 + lane] : -1e30f;
        float c0 = e0;
        #pragma unroll
        for (int off = 16; off; off >>= 1)
            c0 = fmaxf(c0, __shfl_xor_sync(FULL, c0, off));
        float q = act ? __expf(__ldg(&start_t[j]) + e0 - c0) : 0.f;
        float logA = c0;

        for (int s = 0; s < NSEG; ++s) {
            float mrow[10];
            #pragma unroll
            for (int c = 0; c < 10; ++c)
                mrow[c] = act ? sM[s][c][j] : 0.f;
            float sg = (lane < 10) ? sSig[s][lane] : -1e30f;
            float sm = sg;
            #pragma unroll
            for (int off = 16; off; off >>= 1)
                sm = fmaxf(sm, __shfl_xor_sync(FULL, sm, off));
            float u = act ? q * __expf(sg - sm) : 0.f;
            float v = 0.f;
            #pragma unroll
            for (int c = 0; c < 10; ++c)
                v = fmaf(__shfl_sync(FULL, u, c), mrow[c], v);
            q = v;
            logA += sm + sCs[s];
            float ssum = q;
            #pragma unroll
            for (int off = 16; off; off >>= 1)
                ssum += __shfl_xor_sync(FULL, ssum, off);
            logA += __logf(ssum);
            q *= (1.0f / ssum);
        }

        float r = act ? q * __expf(__ldg(&end_t[j])) : 0.f;
        #pragma unroll
        for (int off = 16; off; off >>= 1) r += __shfl_xor_sync(FULL, r, off);
        float denom = logA + __logf(r);

        if (lane == 0) atomicAdd(out, -(numv - denom));
    }
}

// ---------------------------------------------------------------------------
extern "C" void kernel_launch(void* const* d_in, const int* in_sizes, int n_in,
                              void* d_out, int out_size) {
    const float* emb     = (const float*)d_in[0];  // (32,1024,1024) f32
    const int*   mask    = (const int*)  d_in[1];  // (32,1024) i32
    const int*   labels  = (const int*)  d_in[2];  // (32,1024) i32
    const float* conv_w  = (const float*)d_in[3];  // (10,1024,3)
    const float* conv_b  = (const float*)d_in[4];  // (10,)
    const float* start_t = (const float*)d_in[5];  // (10,)
    const float* end_t   = (const float*)d_in[6];  // (10,)
    const float* trans   = (const float*)d_in[7];  // (10,10)
    float* out = (float*)d_out;

    repack_w2_kernel<<<128, 256>>>(conv_w, out);      // also zeroes out[0]
    conv_mma_kernel<<<(NROWS / BM) * KSPLIT, 128>>>(emb);  // 2048 blocks
    crf_seg_kernel<<<BB * NSEG, 128>>>(mask, trans, conv_b);  // fused emissions+scan
    crf_combine_kernel<<<BB, 128>>>(mask, labels, start_t, end_t, trans, out);
}